// round 17
// baseline (speedup 1.0000x reference)
#include <cuda_runtime.h>
#include <cuda_bf16.h>
#include <cstdint>

// Problem constants  (B,T,D,H,L,F = 128,512,32,128,3,4)
#define BATCH 128
#define TT    512
#define DIN   32
#define HID   128
#define GATES 512   // 4*HID
#define FOUT  4

typedef unsigned long long ull;

// ---------------------------------------------------------------------------
// Device scratch
// ---------------------------------------------------------------------------
__device__ float g_pre[BATCH * TT * GATES];
__device__ float g_hs0[BATCH * TT * HID];
__device__ float g_hs1[BATCH * TT * HID];

// ---------------------------------------------------------------------------
// Packed f32x2 helpers (sm_100+)
// ---------------------------------------------------------------------------
__device__ __forceinline__ ull pack2(float lo, float hi) {
    ull r;
    asm("mov.b64 %0, {%1, %2};" : "=l"(r) : "f"(lo), "f"(hi));
    return r;
}
__device__ __forceinline__ void unpack2(ull v, float& lo, float& hi) {
    asm("mov.b64 {%0, %1}, %2;" : "=f"(lo), "=f"(hi) : "l"(v));
}
__device__ __forceinline__ void ffma2(ull& d, ull a, ull b) {
    asm("fma.rn.f32x2 %0, %1, %2, %0;" : "+l"(d) : "l"(a), "l"(b));
}

// MUFU.TANH-based activations (verified R16, rel 3.4e-7)
__device__ __forceinline__ float mufu_tanh(float x) {
    float y;
    asm("tanh.approx.f32 %0, %1;" : "=f"(y) : "f"(x));
    return y;
}
__device__ __forceinline__ float mufu_sigmoid(float x) {
    return fmaf(0.5f, mufu_tanh(0.5f * x), 0.5f);
}

// tf32 helpers
__device__ __forceinline__ uint32_t to_tf32(float x) {
    uint32_t r;
    asm("cvt.rna.tf32.f32 %0, %1;" : "=r"(r) : "f"(x));
    return r;
}
__device__ __forceinline__ void mma_tf32(float* d, uint4 a, uint2 b) {
    asm volatile("mma.sync.aligned.m16n8k8.row.col.f32.tf32.tf32.f32 "
        "{%0,%1,%2,%3}, {%4,%5,%6,%7}, {%8,%9}, {%0,%1,%2,%3};"
        : "+f"(d[0]), "+f"(d[1]), "+f"(d[2]), "+f"(d[3])
        : "r"(a.x), "r"(a.y), "r"(a.z), "r"(a.w), "r"(b.x), "r"(b.y));
}

// ---------------------------------------------------------------------------
// FFMA2 GEMM (kept for K=32 layer-0 pre-GEMM; verified)
// ---------------------------------------------------------------------------
#define GBM 128
#define GBN 128
#define GBK 16

__global__ void __launch_bounds__(256) gemm_bias_kernel(
    const float* __restrict__ A,
    const float* __restrict__ W,
    const float* __restrict__ bi,
    const float* __restrict__ bh,
    float* __restrict__ out,
    int K)
{
    __shared__ float As[2][GBK][GBM];
    __shared__ float Ws[2][GBK][GBN];

    const int bm = blockIdx.x;
    const int bn = blockIdx.y;
    const int tid = threadIdx.x;
    const int tx = tid & 15;
    const int ty = tid >> 4;

    const int lrow = tid >> 1;
    const int lq   = (tid & 1) * 2;

    const float* Ab = A + (size_t)(bm * GBM) * K;
    const float* Wb = W + (size_t)(bn * GBN) * K;

    ull acc[8][4];
    {
#pragma unroll
        for (int j = 0; j < 4; j++) {
            int n = bn * GBN + 2 * tx + 32 * j;
            ull bp = pack2(__ldg(&bi[n]) + __ldg(&bh[n]),
                           __ldg(&bi[n + 1]) + __ldg(&bh[n + 1]));
#pragma unroll
            for (int i = 0; i < 8; i++) acc[i][j] = bp;
        }
    }

    const int nb = K / GBK;

    float4 avr[2], wvr[2];
#pragma unroll
    for (int h = 0; h < 2; h++) {
        int kb = (lq + h) * 4;
        avr[h] = *(const float4*)(Ab + (size_t)lrow * K + kb);
        wvr[h] = *(const float4*)(Wb + (size_t)lrow * K + kb);
    }
#pragma unroll
    for (int h = 0; h < 2; h++) {
        int kb = (lq + h) * 4;
        As[0][kb + 0][lrow] = avr[h].x; As[0][kb + 1][lrow] = avr[h].y;
        As[0][kb + 2][lrow] = avr[h].z; As[0][kb + 3][lrow] = avr[h].w;
        Ws[0][kb + 0][lrow] = wvr[h].x; Ws[0][kb + 1][lrow] = wvr[h].y;
        Ws[0][kb + 2][lrow] = wvr[h].z; Ws[0][kb + 3][lrow] = wvr[h].w;
    }
    __syncthreads();

    for (int it = 0; it < nb; it++) {
        const int cur = it & 1;
        const bool has_next = (it + 1 < nb);

        if (has_next) {
            int k0 = (it + 1) * GBK;
#pragma unroll
            for (int h = 0; h < 2; h++) {
                int kb = (lq + h) * 4;
                avr[h] = *(const float4*)(Ab + (size_t)lrow * K + k0 + kb);
                wvr[h] = *(const float4*)(Wb + (size_t)lrow * K + k0 + kb);
            }
        }

#pragma unroll
        for (int k = 0; k < GBK; k++) {
            const ull* wrow = (const ull*)&Ws[cur][k][0];
            ull w0 = wrow[tx];
            ull w1 = wrow[tx + 16];
            ull w2 = wrow[tx + 32];
            ull w3 = wrow[tx + 48];
            float4 a0 = *(const float4*)&As[cur][k][ty * 8];
            float4 a1 = *(const float4*)&As[cur][k][ty * 8 + 4];
            ull ap[8];
            ap[0] = pack2(a0.x, a0.x); ap[1] = pack2(a0.y, a0.y);
            ap[2] = pack2(a0.z, a0.z); ap[3] = pack2(a0.w, a0.w);
            ap[4] = pack2(a1.x, a1.x); ap[5] = pack2(a1.y, a1.y);
            ap[6] = pack2(a1.z, a1.z); ap[7] = pack2(a1.w, a1.w);
#pragma unroll
            for (int i = 0; i < 8; i++) {
                ffma2(acc[i][0], ap[i], w0);
                ffma2(acc[i][1], ap[i], w1);
                ffma2(acc[i][2], ap[i], w2);
                ffma2(acc[i][3], ap[i], w3);
            }
        }

        if (has_next) {
            const int alt = cur ^ 1;
#pragma unroll
            for (int h = 0; h < 2; h++) {
                int kb = (lq + h) * 4;
                As[alt][kb + 0][lrow] = avr[h].x; As[alt][kb + 1][lrow] = avr[h].y;
                As[alt][kb + 2][lrow] = avr[h].z; As[alt][kb + 3][lrow] = avr[h].w;
                Ws[alt][kb + 0][lrow] = wvr[h].x; Ws[alt][kb + 1][lrow] = wvr[h].y;
                Ws[alt][kb + 2][lrow] = wvr[h].z; Ws[alt][kb + 3][lrow] = wvr[h].w;
            }
            __syncthreads();
        }
    }

    const int m0 = bm * GBM + ty * 8;
#pragma unroll
    for (int i = 0; i < 8; i++) {
#pragma unroll
        for (int j = 0; j < 4; j++) {
            float lo, hi;
            unpack2(acc[i][j], lo, hi);
            int n = bn * GBN + 2 * tx + 32 * j;
            *(float2*)&out[(size_t)(m0 + i) * GATES + n] = make_float2(lo, hi);
        }
    }
}

// ---------------------------------------------------------------------------
// tf32 tensor-core GEMM for K=128: out[m][n] = sum_k A[m][k]W[n][k] + bi + bh
// CTA tile 128x128, full K in one pass. 8 warps (2x4), warp tile 64x32,
// 4x4 m16n8k8 tiles, 16 k-steps. A/W staged in frag-permuted smem so each
// thread's fragment is one LDS.128 / LDS.64 (lane-consecutive, conflict-free).
// Grid (bn=4, bm=512): bn-fastest so A tiles are shared in L2.
// ---------------------------------------------------------------------------
#define TGK 128
#define TF32_SMEM_BYTES (8*16*32*4*4 + 16*16*32*2*4)   // 64KB + 64KB = 128KB

__global__ void __launch_bounds__(256) gemm_tf32_kernel(
    const float* __restrict__ A,
    const float* __restrict__ W,
    const float* __restrict__ bi,
    const float* __restrict__ bh,
    float* __restrict__ out)
{
    extern __shared__ uint32_t tsmem[];
    uint32_t* Ap = tsmem;                   // [mt8][ks16][lane32][4]
    uint32_t* Bp = tsmem + 8 * 16 * 32 * 4; // [nt16][ks16][lane32][2]

    const int bn = blockIdx.x;    // 0..3
    const int bm = blockIdx.y;    // 0..511
    const int tid = threadIdx.x;
    const int wid = tid >> 5;
    const int lane = tid & 31;
    const int wm = wid & 1;       // warp m-row (0..1)
    const int wn = wid >> 1;      // warp n-col (0..3)

    const int m0 = bm * 128;
    const int n0 = bn * 128;

    // ---- fill A (frag-permuted, tf32-converted) ----
    {
        const int row = tid >> 1;               // 0..127 local m
        const int kbase = (tid & 1) * 64;
        const float* src = A + (size_t)(m0 + row) * TGK + kbase;
        const int mt = row >> 4;
        const int r  = row & 15;
        const int gi = r & 7;
        const int ibase = r >> 3;               // 0 or 1
#pragma unroll
        for (int q = 0; q < 16; q++) {
            float4 v = *(const float4*)(src + q * 4);
            float vv[4] = {v.x, v.y, v.z, v.w};
            int k0 = kbase + q * 4;
#pragma unroll
            for (int e = 0; e < 4; e++) {
                int k = k0 + e;
                int ks = k >> 3;
                int c = k & 7;
                int i = ibase + ((c >= 4) ? 2 : 0);
                int ln = gi * 4 + (c & 3);
                Ap[(((mt * 16 + ks) * 32) + ln) * 4 + i] = to_tf32(vv[e]);
            }
        }
    }
    // ---- fill W (B frags) ----
    {
        const int row = tid >> 1;               // 0..127 local n
        const int kbase = (tid & 1) * 64;
        const float* src = W + (size_t)(n0 + row) * TGK + kbase;
        const int nt = row >> 3;
        const int cl = row & 7;
#pragma unroll
        for (int q = 0; q < 16; q++) {
            float4 v = *(const float4*)(src + q * 4);
            float vv[4] = {v.x, v.y, v.z, v.w};
            int k0 = kbase + q * 4;
#pragma unroll
            for (int e = 0; e < 4; e++) {
                int k = k0 + e;
                int ks = k >> 3;
                int r = k & 7;
                int j = r >> 2;
                int ln = cl * 4 + (r & 3);
                Bp[(((nt * 16 + ks) * 32) + ln) * 2 + j] = to_tf32(vv[e]);
            }
        }
    }
    __syncthreads();

    // ---- accumulators pre-loaded with bias ----
    float acc[4][4][4];
    {
        const int tig = lane & 3;
#pragma unroll
        for (int nt = 0; nt < 4; nt++) {
            int ncol = n0 + wn * 32 + nt * 8 + 2 * tig;
            float b0 = __ldg(&bi[ncol]) + __ldg(&bh[ncol]);
            float b1 = __ldg(&bi[ncol + 1]) + __ldg(&bh[ncol + 1]);
#pragma unroll
            for (int mt = 0; mt < 4; mt++) {
                acc[mt][nt][0] = b0; acc[mt][nt][1] = b1;
                acc[mt][nt][2] = b0; acc[mt][nt][3] = b1;
            }
        }
    }

    // ---- main K loop ----
#pragma unroll
    for (int ks = 0; ks < 16; ks++) {
        uint4 af[4];
        uint2 bf[4];
#pragma unroll
        for (int mt = 0; mt < 4; mt++)
            af[mt] = *(const uint4*)&Ap[(((wm * 4 + mt) * 16 + ks) * 32 + lane) * 4];
#pragma unroll
        for (int nt = 0; nt < 4; nt++)
            bf[nt] = *(const uint2*)&Bp[(((wn * 4 + nt) * 16 + ks) * 32 + lane) * 2];
#pragma unroll
        for (int mt = 0; mt < 4; mt++)
#pragma unroll
            for (int nt = 0; nt < 4; nt++)
                mma_tf32(acc[mt][nt], af[mt], bf[nt]);
    }

    // ---- epilogue (float2 stores) ----
    {
        const int gid = lane >> 2;
        const int tig = lane & 3;
#pragma unroll
        for (int mt = 0; mt < 4; mt++) {
            int m = m0 + wm * 64 + mt * 16 + gid;
#pragma unroll
            for (int nt = 0; nt < 4; nt++) {
                int n = n0 + wn * 32 + nt * 8 + 2 * tig;
                *(float2*)&out[(size_t)m * GATES + n] =
                    make_float2(acc[mt][nt][0], acc[mt][nt][1]);
                *(float2*)&out[(size_t)(m + 8) * GATES + n] =
                    make_float2(acc[mt][nt][2], acc[mt][nt][3]);
            }
        }
    }
}

// ---------------------------------------------------------------------------
// LSTM v7 (R15/R16 structure — measured best) with MUFU.TANH activations.
// ---------------------------------------------------------------------------
#define LTHREADS 512
#define LSTM_SMEM_BYTES (16 * 512 * 8 + 1024 * 4 + HID * 4)

__global__ void __launch_bounds__(LTHREADS, 1) lstm_kernel(
    const float* __restrict__ pre,   // [B][T][512]
    const float* __restrict__ whh,   // [512][128]
    float* __restrict__ hs)          // [B][T][128]
{
    extern __shared__ char smemraw[];
    ull*   wsu  = (ull*)smemraw;                       // [16][512]
    float* sbuf = (float*)(smemraw + 16 * 512 * 8);    // [2][512] partials
    float* hvec = sbuf + 1024;                         // [128], 16B aligned

    const int b = blockIdx.x;
    const int idx = threadIdx.x;
    const int half = idx >> 8;
    const int tid = idx & 255;

    ull wr[32];
    ull ws_lo[16];
    {
        const float4* r4 = (const float4*)(whh + (size_t)(256 + tid) * HID);
#pragma unroll
        for (int i = 0; i < 16; i++) {
            float4 v = r4[16 * half + i];
            wr[2 * i]     = pack2(v.x, v.y);
            wr[2 * i + 1] = pack2(v.z, v.w);
        }
        const float4* s4 = (const float4*)(whh + (size_t)tid * HID);
#pragma unroll
        for (int i = 0; i < 8; i++) {
            float4 v = s4[16 * half + i];
            ws_lo[2 * i]     = pack2(v.x, v.y);
            ws_lo[2 * i + 1] = pack2(v.z, v.w);
        }
#pragma unroll
        for (int i = 0; i < 8; i++) {
            float4 v = s4[16 * half + 8 + i];
            wsu[(2 * i) * 512 + idx]     = pack2(v.x, v.y);
            wsu[(2 * i + 1) * 512 + idx] = pack2(v.z, v.w);
        }
    }
    if (idx < HID) hvec[idx] = 0.f;
    float c = 0.f;
    __syncthreads();

    const float* preb = pre + (size_t)b * TT * GATES;
    float* hsb = hs + (size_t)b * TT * HID;

    float p_s = 0.f, p_r = 0.f;
    if (half == 0) { p_s = preb[tid]; p_r = preb[256 + tid]; }

#pragma unroll 1
    for (int t = 0; t < TT; t++) {
        ull ar0 = 0, ar1 = 0, as0 = 0, as1 = 0;

        const float c_s = p_s, c_r = p_r;
        if (half == 0 && t + 1 < TT) {
            const float* pn = preb + (size_t)(t + 1) * GATES;
            p_s = pn[tid];
            p_r = pn[256 + tid];
        }

        const ulonglong2* hu4 = (const ulonglong2*)hvec;
#pragma unroll
        for (int i = 0; i < 16; i++) {
            ulonglong2 ha = hu4[16 * half + i];
            ffma2(ar0, wr[2 * i],     ha.x);
            ffma2(ar1, wr[2 * i + 1], ha.y);
            if (i < 8) {
                ffma2(as0, ws_lo[2 * i],     ha.x);
                ffma2(as1, ws_lo[2 * i + 1], ha.y);
            } else {
                ull w0 = wsu[(2 * (i - 8)) * 512 + idx];
                ull w1 = wsu[(2 * (i - 8) + 1) * 512 + idx];
                ffma2(as0, w0, ha.x);
                ffma2(as1, w1, ha.y);
            }
        }

        float xl, xh, yl, yh;
        unpack2(ar0, xl, xh); unpack2(ar1, yl, yh);
        float part_r = c_r + ((xl + xh) + (yl + yh));
        unpack2(as0, xl, xh); unpack2(as1, yl, yh);
        float part_s = c_s + ((xl + xh) + (yl + yh));

        sbuf[half * 512 + tid]       = part_s;
        sbuf[half * 512 + 256 + tid] = part_r;
        __syncthreads();

        if (idx < HID) {
            const int u = idx;
            float gi = sbuf[u]       + sbuf[512 + u];
            float gf = sbuf[128 + u] + sbuf[640 + u];
            float gg = sbuf[256 + u] + sbuf[768 + u];
            float go = sbuf[384 + u] + sbuf[896 + u];
            float iv = mufu_sigmoid(gi);
            float fv = mufu_sigmoid(gf);
            float gv = mufu_tanh(gg);
            float ov = mufu_sigmoid(go);
            c = fmaf(fv, c, iv * gv);
            float h = ov * mufu_tanh(c);
            hvec[u] = h;
            hsb[(size_t)t * HID + u] = h;
        }
        __syncthreads();
    }
}

// ---------------------------------------------------------------------------
// Fused attention pooling + MLP head (verified R16)
// ---------------------------------------------------------------------------
__global__ void __launch_bounds__(128) attn_mlp_kernel(
    const float* __restrict__ hs,
    const float* __restrict__ w_attn,
    const float* __restrict__ b_attn,
    const float* __restrict__ w1, const float* __restrict__ b1,
    const float* __restrict__ w2, const float* __restrict__ b2,
    float* __restrict__ out)
{
    __shared__ float wv[HID];
    __shared__ float lg[TT];
    __shared__ float red[4];
    __shared__ float cs[HID];
    __shared__ float h1[64];

    const int b = blockIdx.x;
    const int tid = threadIdx.x;

    wv[tid] = w_attn[tid];
    __syncthreads();

    const float* hb = hs + (size_t)b * TT * HID;
    const float battn = __ldg(&b_attn[0]);

    for (int t = tid; t < TT; t += 128) {
        const float4* row = (const float4*)(hb + (size_t)t * HID);
        const float4* wr4 = (const float4*)wv;
        float s = 0.f;
#pragma unroll
        for (int k = 0; k < HID / 4; k++) {
            float4 v = row[k];
            float4 w = wr4[k];
            s = fmaf(v.x, w.x, s);
            s = fmaf(v.y, w.y, s);
            s = fmaf(v.z, w.z, s);
            s = fmaf(v.w, w.w, s);
        }
        lg[t] = s + battn;
    }
    __syncthreads();

    float m = -1e30f;
    for (int t = tid; t < TT; t += 128) m = fmaxf(m, lg[t]);
#pragma unroll
    for (int o = 16; o > 0; o >>= 1) m = fmaxf(m, __shfl_xor_sync(0xffffffffu, m, o));
    if ((tid & 31) == 0) red[tid >> 5] = m;
    __syncthreads();
    m = fmaxf(fmaxf(red[0], red[1]), fmaxf(red[2], red[3]));
    __syncthreads();

    float z = 0.f;
    for (int t = tid; t < TT; t += 128) {
        float e = __expf(lg[t] - m);
        lg[t] = e;
        z += e;
    }
#pragma unroll
    for (int o = 16; o > 0; o >>= 1) z += __shfl_xor_sync(0xffffffffu, z, o);
    __syncthreads();
    if ((tid & 31) == 0) red[tid >> 5] = z;
    __syncthreads();
    z = red[0] + red[1] + red[2] + red[3];
    const float inv = 1.f / z;

    float acc = 0.f;
    for (int t = 0; t < TT; t++)
        acc = fmaf(lg[t], hb[(size_t)t * HID + tid], acc);
    cs[tid] = acc * inv;
    __syncthreads();

    if (tid < 64) {
        const float* wr = w1 + (size_t)tid * HID;
        float s = __ldg(&b1[tid]);
#pragma unroll 8
        for (int k = 0; k < HID; k++) s = fmaf(wr[k], cs[k], s);
        h1[tid] = fmaxf(s, 0.f);
    }
    __syncthreads();

    if (tid < FOUT) {
        const float* wr = w2 + (size_t)tid * 64;
        float s = __ldg(&b2[tid]);
#pragma unroll 8
        for (int k = 0; k < 64; k++) s = fmaf(wr[k], h1[k], s);
        out[(size_t)b * FOUT + tid] = s;
    }
}

// ---------------------------------------------------------------------------
// kernel_launch — wiring identical to R5-R16 (verified passing).
// ---------------------------------------------------------------------------
extern "C" void kernel_launch(void* const* d_in, const int* in_sizes, int n_in,
                              void* d_out, int out_size)
{
    const float *x = 0, *w_ih0 = 0, *w_ihr = 0, *w_hh = 0;
    const float *b_ih = 0, *b_hh = 0, *w_attn = 0, *b_attn = 0;
    const float *w1 = 0, *b1 = 0, *w2 = 0, *b2 = 0;

    int unit_bytes = 0, unit_elems = 0;
    for (int i = 0; i < n_in; i++) {
        if (in_sizes[i] == 8388608) unit_bytes = 1;
        if (in_sizes[i] == 2097152) unit_elems = 1;
    }

    if (unit_bytes || unit_elems) {
        const int div = unit_bytes ? 4 : 1;
        for (int i = 0; i < n_in; i++) {
            const float* p = (const float*)d_in[i];
            long long e = (long long)in_sizes[i] / div;
            switch (e) {
                case 2097152: x      = p; break;
                case 196608:  w_hh   = p; break;
                case 131072:  w_ihr  = p; break;
                case 16384:   w_ih0  = p; break;
                case 8192:    w1     = p; break;
                case 1536:    if (!b_ih) b_ih = p; else b_hh = p; break;
                case 256:     w2     = p; break;
                case 128:     w_attn = p; break;
                case 64:      b1     = p; break;
                case 4:       b2     = p; break;
                case 1:       b_attn = p; break;
                default: break;
            }
        }
    }

    if (n_in >= 12) {
        if (!x)      x      = (const float*)d_in[0];
        if (!w_ih0)  w_ih0  = (const float*)d_in[1];
        if (!w_ihr)  w_ihr  = (const float*)d_in[2];
        if (!w_hh)   w_hh   = (const float*)d_in[3];
        if (!b_ih)   b_ih   = (const float*)d_in[4];
        if (!b_hh)   b_hh   = (const float*)d_in[5];
        if (!w_attn) w_attn = (const float*)d_in[6];
        if (!b_attn) b_attn = (const float*)d_in[7];
        if (!w1)     w1     = (const float*)d_in[8];
        if (!b1)     b1     = (const float*)d_in[9];
        if (!w2)     w2     = (const float*)d_in[10];
        if (!b2)     b2     = (const float*)d_in[11];
    }

    float* out = (float*)d_out;

    float *pre = nullptr, *hs0 = nullptr, *hs1 = nullptr;
    cudaGetSymbolAddress((void**)&pre, g_pre);
    cudaGetSymbolAddress((void**)&hs0, g_hs0);
    cudaGetSymbolAddress((void**)&hs1, g_hs1);

    cudaFuncSetAttribute(lstm_kernel,
                         cudaFuncAttributeMaxDynamicSharedMemorySize,
                         LSTM_SMEM_BYTES);
    cudaFuncSetAttribute(gemm_tf32_kernel,
                         cudaFuncAttributeMaxDynamicSharedMemorySize,
                         TF32_SMEM_BYTES);

    dim3 ggrid0(BATCH * TT / GBM, GATES / GBN);   // 512 x 4 (FFMA2, K=32)
    dim3 tgrid(4, BATCH * TT / 128);              // bn-fastest: 4 x 512

    // Layer 0 (K=32: FFMA2 GEMM)
    gemm_bias_kernel<<<ggrid0, 256>>>(x, w_ih0, b_ih + 0 * GATES, b_hh + 0 * GATES, pre, DIN);
    lstm_kernel<<<BATCH, LTHREADS, LSTM_SMEM_BYTES>>>(pre, w_hh + (size_t)0 * GATES * HID, hs0);

    // Layer 1 (K=128: tf32 tensor cores)
    gemm_tf32_kernel<<<tgrid, 256, TF32_SMEM_BYTES>>>(hs0, w_ihr + (size_t)0 * GATES * HID,
                                                      b_ih + 1 * GATES, b_hh + 1 * GATES, pre);
    lstm_kernel<<<BATCH, LTHREADS, LSTM_SMEM_BYTES>>>(pre, w_hh + (size_t)1 * GATES * HID, hs1);

    // Layer 2 (K=128: tf32 tensor cores)
    gemm_tf32_kernel<<<tgrid, 256, TF32_SMEM_BYTES>>>(hs1, w_ihr + (size_t)1 * GATES * HID,
                                                      b_ih + 2 * GATES, b_hh + 2 * GATES, pre);
    lstm_kernel<<<BATCH, LTHREADS, LSTM_SMEM_BYTES>>>(pre, w_hh + (size_t)2 * GATES * HID, hs0);

    // Fused attention pooling + MLP head
    attn_mlp_kernel<<<BATCH, 128>>>(hs0, w_attn, b_attn, w1, b1, w2, b2, out);
}